// round 4
// baseline (speedup 1.0000x reference)
#include <cuda_runtime.h>
#include <math.h>

#define T_  512
#define B_  64
#define E_  256
#define H_  256
#define TB_ (T_ * B_)          // 32768
#define CLU 8                  // CTAs per cluster
#define BG  4                  // batch elements per cluster

typedef unsigned long long ull;

// ---------------- static device scratch ----------------
__device__ float g_Q  [TB_ * E_];
__device__ float g_K  [TB_ * E_];
__device__ float g_S  [B_ * T_ * T_];
__device__ float g_CTX[TB_ * E_];
__device__ float g_CP [TB_ * H_];
__device__ float g_PRE[(long)TB_ * 4 * H_];
__device__ float g_Wall[512 * 1024];       // packed gates, col = j*4+g
__device__ float g_ball[1024];
__device__ float g_WhC[CLU * 256 * 32 * 4];// recurrent W: [rank][k][jl][gate4]

// ---------------- f32x2 helpers ----------------
#define PACKS(d, s) asm("mov.b64 %0, {%1,%1};" : "=l"(d) : "f"(s))
#define UNPK(lo, hi, v) asm("mov.b64 {%0,%1}, %2;" : "=f"(lo), "=f"(hi) : "l"(v))
#define FFMA2(acc, a, b) \
    asm("fma.rn.f32x2 %0, %1, %2, %0;" : "+l"(acc) : "l"(a), "l"(b))
#define ADD2(d, a, b) asm("add.rn.f32x2 %0, %1, %2;" : "=l"(d) : "l"(a), "l"(b))

// ---------------- tf32 split helper ----------------
__device__ __forceinline__ void split_tf32(float x, unsigned& hi, unsigned& lo)
{
    unsigned h;
    asm("cvt.rna.tf32.f32 %0, %1;" : "=r"(h) : "f"(x));
    float lf = x - __uint_as_float(h);
    unsigned l;
    asm("cvt.rna.tf32.f32 %0, %1;" : "=r"(l) : "f"(lf));
    hi = h; lo = l;
}

#define MMA_TF32(c, a, b)                                                         \
    asm volatile("mma.sync.aligned.m16n8k8.row.col.f32.tf32.tf32.f32 "            \
                 "{%0,%1,%2,%3},{%4,%5,%6,%7},{%8,%9},{%0,%1,%2,%3};"             \
                 : "+f"(c[0]), "+f"(c[1]), "+f"(c[2]), "+f"(c[3])                 \
                 : "r"(a[0]), "r"(a[1]), "r"(a[2]), "r"(a[3]),                    \
                   "r"(b[0]), "r"(b[1]))

// ---------------- tensor-core tf32 GEMM (3x split) with reg double-buffer -----
template<bool NT, bool BIAS, bool CONCAT>
__global__ void __launch_bounds__(256, 2) gemm_tc(
    const float* __restrict__ A, const float* __restrict__ A2,
    const float* __restrict__ B, float* __restrict__ C,
    const float* __restrict__ bias,
    int M, int N, int K, int lda, int ldb, int ldc,
    long sA, long sB, long sC)
{
    A += (long)blockIdx.z * sA;
    B += (long)blockIdx.z * sB;
    C += (long)blockIdx.z * sC;

    __shared__ unsigned As_hi[128][20], As_lo[128][20];
    __shared__ unsigned Bs_hi[16][72],  Bs_lo[16][72];

    const int tid  = threadIdx.x;
    const int lane = tid & 31;
    const int warp = tid >> 5;
    const int m0 = blockIdx.y * 128;
    const int n0 = blockIdx.x * 64;
    const int wm = (warp >> 1) * 32;
    const int wn = (warp & 1) * 32;
    const int gq = lane >> 2;
    const int tg = lane & 3;

    const int ar  = tid >> 2;
    const int ac  = (tid & 3) * 4;
    const int bkr = tid >> 4;
    const int bnc = (tid & 15) * 4;
    const int bnr = tid >> 2;
    const int bkc = (tid & 3) * 4;

    float acc[2][4][4];
    #pragma unroll
    for (int i = 0; i < 2; ++i)
        #pragma unroll
        for (int j = 0; j < 4; ++j)
            #pragma unroll
            for (int q = 0; q < 4; ++q) acc[i][j][q] = 0.f;

    auto load_tile = [&](int k0, float4& va0, float4& va1, float4& vb) {
        const float* Ab = A;
        int kc = k0;
        if (CONCAT) { if (k0 >= 256) { Ab = A2; kc = k0 - 256; } }
        va0 = *(const float4*)(Ab + (long)(m0 + ar) * lda + kc + ac);
        va1 = *(const float4*)(Ab + (long)(m0 + ar + 64) * lda + kc + ac);
        if (NT) vb = *(const float4*)(B + (long)(n0 + bnr) * ldb + k0 + bkc);
        else    vb = *(const float4*)(B + (long)(k0 + bkr) * ldb + n0 + bnc);
    };

    float4 va0, va1, vb;
    load_tile(0, va0, va1, vb);

    for (int k0 = 0; k0 < K; k0 += 16) {
        __syncthreads();
        {
            float av[4] = {va0.x, va0.y, va0.z, va0.w};
            #pragma unroll
            for (int q = 0; q < 4; ++q)
                split_tf32(av[q], As_hi[ar][ac + q], As_lo[ar][ac + q]);
            float aw[4] = {va1.x, va1.y, va1.z, va1.w};
            #pragma unroll
            for (int q = 0; q < 4; ++q)
                split_tf32(aw[q], As_hi[ar + 64][ac + q], As_lo[ar + 64][ac + q]);
            float bv[4] = {vb.x, vb.y, vb.z, vb.w};
            if (NT) {
                #pragma unroll
                for (int q = 0; q < 4; ++q)
                    split_tf32(bv[q], Bs_hi[bkc + q][bnr], Bs_lo[bkc + q][bnr]);
            } else {
                #pragma unroll
                for (int q = 0; q < 4; ++q)
                    split_tf32(bv[q], Bs_hi[bkr][bnc + q], Bs_lo[bkr][bnc + q]);
            }
        }
        __syncthreads();

        // prefetch next tile while MMAs run (hides DRAM latency)
        int kn = (k0 + 16 < K) ? k0 + 16 : k0;
        load_tile(kn, va0, va1, vb);

        #pragma unroll
        for (int kk = 0; kk < 16; kk += 8) {
            unsigned ah[2][4], al[2][4], bh[4][2], bl[4][2];
            #pragma unroll
            for (int i = 0; i < 2; ++i) {
                int r = wm + i * 16 + gq;
                ah[i][0] = As_hi[r    ][kk + tg];
                ah[i][1] = As_hi[r + 8][kk + tg];
                ah[i][2] = As_hi[r    ][kk + tg + 4];
                ah[i][3] = As_hi[r + 8][kk + tg + 4];
                al[i][0] = As_lo[r    ][kk + tg];
                al[i][1] = As_lo[r + 8][kk + tg];
                al[i][2] = As_lo[r    ][kk + tg + 4];
                al[i][3] = As_lo[r + 8][kk + tg + 4];
            }
            #pragma unroll
            for (int j = 0; j < 4; ++j) {
                int n = wn + j * 8 + gq;
                bh[j][0] = Bs_hi[kk + tg    ][n];
                bh[j][1] = Bs_hi[kk + tg + 4][n];
                bl[j][0] = Bs_lo[kk + tg    ][n];
                bl[j][1] = Bs_lo[kk + tg + 4][n];
            }
            #pragma unroll
            for (int i = 0; i < 2; ++i)
                #pragma unroll
                for (int j = 0; j < 4; ++j) {
                    MMA_TF32(acc[i][j], ah[i], bh[j]);
                    MMA_TF32(acc[i][j], al[i], bh[j]);
                    MMA_TF32(acc[i][j], ah[i], bl[j]);
                }
        }
    }

    #pragma unroll
    for (int i = 0; i < 2; ++i)
        #pragma unroll
        for (int j = 0; j < 4; ++j) {
            int m = m0 + wm + i * 16 + gq;
            int n = n0 + wn + j * 8 + 2 * tg;
            float2 v0 = make_float2(acc[i][j][0], acc[i][j][1]);
            float2 v1 = make_float2(acc[i][j][2], acc[i][j][3]);
            if (BIAS) {
                float b0 = bias[n], b1 = bias[n + 1];
                v0.x += b0; v0.y += b1;
                v1.x += b0; v1.y += b1;
            }
            *(float2*)(C + (long)m * ldc + n)       = v0;
            *(float2*)(C + (long)(m + 8) * ldc + n) = v1;
        }
}

// ---------------- softmax over rows of length 512 ----------
__global__ void __launch_bounds__(128) softmax_k(float* __restrict__ S)
{
    float* p = S + (long)blockIdx.x * 512;
    int tid = threadIdx.x;
    float v[4];
    float m = -1e30f;
    #pragma unroll
    for (int i = 0; i < 4; ++i) { v[i] = p[tid + 128 * i] * 0.0625f; m = fmaxf(m, v[i]); }
    __shared__ float red[128];
    red[tid] = m; __syncthreads();
    for (int s = 64; s > 0; s >>= 1) { if (tid < s) red[tid] = fmaxf(red[tid], red[tid + s]); __syncthreads(); }
    m = red[0]; __syncthreads();
    float sum = 0.f;
    #pragma unroll
    for (int i = 0; i < 4; ++i) { v[i] = expf(v[i] - m); sum += v[i]; }
    red[tid] = sum; __syncthreads();
    for (int s = 64; s > 0; s >>= 1) { if (tid < s) red[tid] += red[tid + s]; __syncthreads(); }
    float inv = 1.f / red[0];
    #pragma unroll
    for (int i = 0; i < 4; ++i) p[tid + 128 * i] = v[i] * inv;
}

// ---------------- pack weights ----------------
__global__ void pack_init_k(const float* __restrict__ Wf, const float* __restrict__ Wi,
                            const float* __restrict__ Wu, const float* __restrict__ Wo,
                            const float* __restrict__ bf, const float* __restrict__ bi,
                            const float* __restrict__ bu, const float* __restrict__ bo)
{
    int idx = blockIdx.x * blockDim.x + threadIdx.x;
    int nt = gridDim.x * blockDim.x;
    // recurrent weights: [rank][k][jl][g]
    for (int i = idx; i < CLU * 256 * 32 * 4; i += nt) {
        int r  = i >> 15;
        int k  = (i >> 7) & 255;
        int jl = (i >> 2) & 31;
        int g  = i & 3;
        const float* W = (g == 0) ? Wf : (g == 1) ? Wi : (g == 2) ? Wu : Wo;
        g_WhC[i] = W[(E_ + k) * H_ + r * 32 + jl];
    }
    // fused PRE weights, gate-interleaved: col = j*4+g
    for (int i = idx; i < 512 * 1024; i += nt) {
        int k = i >> 10;
        int col = i & 1023;
        int j = col >> 2, g = col & 3;
        const float* W = (g == 0) ? Wf : (g == 1) ? Wi : (g == 2) ? Wu : Wo;
        g_Wall[i] = W[k * 256 + j];
    }
    for (int i = idx; i < 1024; i += nt) {
        int g = i & 3;
        const float* b = (g == 0) ? bf : (g == 1) ? bi : (g == 2) ? bu : bo;
        g_ball[i] = b[i >> 2];
    }
}

__device__ __forceinline__ float sigf(float x)  { return 1.f / (1.f + __expf(-x)); }
__device__ __forceinline__ float tanhf_(float x){ return 2.f / (1.f + __expf(-2.f * x)) - 1.f; }

// ---------------- cluster LSTM recurrence (f32x2) ----------------
// part layout: float4 part[b*270 + ks*33 + jl]  (b-stride 270 -> conflict-free reads)
#define PART_AT(b, s, j) ((b) * 270 + (s) * 33 + (j))

__global__ void __launch_bounds__(256, 1) __cluster_dims__(CLU, 1, 1)
recur3_k(const float* __restrict__ PRE, float* __restrict__ out)
{
    extern __shared__ float4 sm4[];
    float4* ws4   = sm4;            // [256 k][32 jl] (gate4)  8192 fl4
    float4* hs4   = sm4 + 8192;     // [2 buf][256 k] (b4)      512 fl4
    float4* part4 = sm4 + 8704;     // 1080 fl4 (PART_AT)

    const int tid = threadIdx.x;
    unsigned rank;
    asm("mov.u32 %0, %%cluster_ctarank;" : "=r"(rank));
    const int bg0 = (blockIdx.x / CLU) * BG;

    const float4* Wsrc = (const float4*)g_WhC + (long)rank * 8192;
    for (int m = tid; m < 8192; m += 256) ws4[m] = Wsrc[m];
    for (int m = tid; m < 512; m += 256) hs4[m] = make_float4(0.f, 0.f, 0.f, 0.f);

    const int jl = tid & 31;
    const int ks = tid >> 5;

    const bool epi = tid < 128;
    const int  eb  = tid & 3;
    const int  ejl = tid >> 2;
    const int  jg  = rank * 32 + ejl;

    float creg = 0.f, hlast = 0.f;
    float4 pre = make_float4(0.f, 0.f, 0.f, 0.f);
    if (epi)
        pre = *(const float4*)(PRE + ((long)0 * B_ + bg0 + eb) * 1024 + jg * 4);

    const unsigned hs_u32 = (unsigned)__cvta_generic_to_shared(hs4);

    asm volatile("barrier.cluster.arrive.aligned;" ::: "memory");
    asm volatile("barrier.cluster.wait.aligned;"   ::: "memory");

    for (int t = 0; t < T_; ++t) {
        const int buf = t & 1;
        const float4* hp = hs4 + buf * 256 + ks * 32;
        const float4* wp = ws4 + (ks * 32) * 32 + jl;

        ull acc0 = 0, acc1 = 0, acc2 = 0, acc3 = 0, acc4 = 0, acc5 = 0, acc6 = 0, acc7 = 0;
        #pragma unroll 8
        for (int u = 0; u < 32; ++u) {
            float4 hv = hp[u];                               // 4 batches at k
            ulonglong2 wv = *(const ulonglong2*)(wp + u * 32); // (wf,wi),(wu,wo)
            ull h0, h1, h2, h3;
            PACKS(h0, hv.x); PACKS(h1, hv.y); PACKS(h2, hv.z); PACKS(h3, hv.w);
            FFMA2(acc0, h0, wv.x); FFMA2(acc1, h0, wv.y);
            FFMA2(acc2, h1, wv.x); FFMA2(acc3, h1, wv.y);
            FFMA2(acc4, h2, wv.x); FFMA2(acc5, h2, wv.y);
            FFMA2(acc6, h3, wv.x); FFMA2(acc7, h3, wv.y);
        }
        {
            ulonglong2* pp;
            pp = (ulonglong2*)&part4[PART_AT(0, ks, jl)]; pp->x = acc0; pp->y = acc1;
            pp = (ulonglong2*)&part4[PART_AT(1, ks, jl)]; pp->x = acc2; pp->y = acc3;
            pp = (ulonglong2*)&part4[PART_AT(2, ks, jl)]; pp->x = acc4; pp->y = acc5;
            pp = (ulonglong2*)&part4[PART_AT(3, ks, jl)]; pp->x = acc6; pp->y = acc7;
        }
        __syncthreads();

        if (epi) {
            // prefetch next step's PRE first (independent of reduce)
            int tn = (t < T_ - 1) ? t + 1 : t;
            float4 pren = *(const float4*)(PRE + ((long)tn * B_ + bg0 + eb) * 1024 + jg * 4);

            ulonglong2 s = *(const ulonglong2*)&part4[PART_AT(eb, 0, ejl)];
            #pragma unroll
            for (int q = 1; q < 8; ++q) {
                ulonglong2 p = *(const ulonglong2*)&part4[PART_AT(eb, q, ejl)];
                ADD2(s.x, s.x, p.x);
                ADD2(s.y, s.y, p.y);
            }
            float sf, si, su, so;
            UNPK(sf, si, s.x);
            UNPK(su, so, s.y);
            float fg = sigf  (sf + pre.x);
            float ig = sigf  (si + pre.y);
            float ug = tanhf_(su + pre.z);
            float og = sigf  (so + pre.w);
            creg  = fg * creg + ig * ug;
            hlast = og * tanhf_(creg);
            out[((long)t * B_ + bg0 + eb) * H_ + jg] = hlast;

            unsigned laddr = hs_u32 + ((((buf ^ 1) * 256 + jg) * 4 + eb) << 2);
            #pragma unroll
            for (int r2 = 0; r2 < CLU; ++r2) {
                unsigned ra;
                asm volatile("mapa.shared::cluster.u32 %0, %1, %2;"
                             : "=r"(ra) : "r"(laddr), "r"(r2));
                asm volatile("st.shared::cluster.f32 [%0], %1;"
                             :: "r"(ra), "f"(hlast) : "memory");
            }
            pre = pren;
        }

        asm volatile("barrier.cluster.arrive.aligned;" ::: "memory");
        asm volatile("barrier.cluster.wait.aligned;"   ::: "memory");
    }

    if (epi) {
        out[(long)TB_ * H_ + (bg0 + eb) * H_ + jg] = hlast;                 // hx
        out[(long)TB_ * H_ + (long)B_ * H_ + (bg0 + eb) * H_ + jg] = creg;  // cx
    }
}

// ---------------- launch ----------------
extern "C" void kernel_launch(void* const* d_in, const int* in_sizes, int n_in,
                              void* d_out, int out_size)
{
    const float* inputs = (const float*)d_in[0];
    const float* rot    = (const float*)d_in[1];
    const float* ent    = (const float*)d_in[2];
    const float* Wf = (const float*)d_in[3];  const float* bf = (const float*)d_in[4];
    const float* Wi = (const float*)d_in[5];  const float* bi = (const float*)d_in[6];
    const float* Wu = (const float*)d_in[7];  const float* bu = (const float*)d_in[8];
    const float* Wo = (const float*)d_in[9];  const float* bo = (const float*)d_in[10];
    const float* Wc = (const float*)d_in[11]; const float* bc = (const float*)d_in[12];
    float* out = (float*)d_out;

    float *Q, *K, *S, *CTX, *CP, *PRE, *Wall, *ball;
    cudaGetSymbolAddress((void**)&Q,    g_Q);
    cudaGetSymbolAddress((void**)&K,    g_K);
    cudaGetSymbolAddress((void**)&S,    g_S);
    cudaGetSymbolAddress((void**)&CTX,  g_CTX);
    cudaGetSymbolAddress((void**)&CP,   g_CP);
    cudaGetSymbolAddress((void**)&PRE,  g_PRE);
    cudaGetSymbolAddress((void**)&Wall, g_Wall);
    cudaGetSymbolAddress((void**)&ball, g_ball);

    const int RSMEM = (8192 + 512 + 1080) * 16;   // 156544 B
    cudaFuncSetAttribute(recur3_k, cudaFuncAttributeMaxDynamicSharedMemorySize, RSMEM);

    pack_init_k<<<256, 256>>>(Wf, Wi, Wu, Wo, bf, bi, bu, bo);

    gemm_tc<false, false, false><<<dim3(E_ / 64, TB_ / 128, 1), 256>>>(
        inputs, nullptr, rot, Q, nullptr, TB_, E_, E_, E_, E_, E_, 0, 0, 0);
    gemm_tc<false, false, false><<<dim3(E_ / 64, TB_ / 128, 1), 256>>>(
        inputs, nullptr, ent, K, nullptr, TB_, E_, E_, E_, E_, E_, 0, 0, 0);

    gemm_tc<true, false, false><<<dim3(T_ / 64, T_ / 128, B_), 256>>>(
        Q, nullptr, K, S, nullptr, T_, T_, E_, B_ * E_, B_ * E_, T_,
        (long)E_, (long)E_, (long)T_ * T_);

    softmax_k<<<B_ * T_, 128>>>(S);

    gemm_tc<false, false, false><<<dim3(E_ / 64, T_ / 128, B_), 256>>>(
        S, nullptr, inputs, CTX, nullptr, T_, E_, T_, T_, B_ * E_, B_ * E_,
        (long)T_ * T_, (long)E_, (long)E_);

    gemm_tc<false, true, false><<<dim3(H_ / 64, TB_ / 128, 1), 256>>>(
        CTX, nullptr, Wc, CP, bc, TB_, H_, E_, E_, H_, H_, 0, 0, 0);

    gemm_tc<false, true, true><<<dim3(1024 / 64, TB_ / 128, 1), 256>>>(
        inputs, CP, Wall, PRE, ball, TB_, 1024, 512, E_, 1024, 1024, 0, 0, 0);

    recur3_k<<<128, 256, RSMEM>>>(PRE, out);
    (void)in_sizes; (void)n_in; (void)out_size;
}

// round 5
// speedup vs baseline: 1.1105x; 1.1105x over previous
#include <cuda_runtime.h>
#include <math.h>

#define T_  512
#define B_  64
#define E_  256
#define H_  256
#define TB_ (T_ * B_)          // 32768
#define CLU 8                  // CTAs per cluster
#define BG  4                  // batch elements per cluster

// ---------------- static device scratch ----------------
__device__ float g_Q  [TB_ * E_];
__device__ float g_K  [TB_ * E_];
__device__ float g_S  [B_ * T_ * T_];
__device__ float g_CTX[TB_ * E_];
__device__ float g_CP [TB_ * H_];
__device__ float g_PRE[(long)TB_ * 4 * H_];
__device__ float g_Wall[512 * 1024];       // packed [Wf|Wi|Wu|Wo] as (512, 1024)
__device__ float g_ball[1024];
__device__ float g_WhC[CLU * 256 * 32 * 4];// recurrent W: [rank][k][jl][gate4]

// ---------------- tf32 split helper ----------------
__device__ __forceinline__ void split_tf32(float x, unsigned& hi, unsigned& lo)
{
    unsigned h;
    asm("cvt.rna.tf32.f32 %0, %1;" : "=r"(h) : "f"(x));
    float lf = x - __uint_as_float(h);
    unsigned l;
    asm("cvt.rna.tf32.f32 %0, %1;" : "=r"(l) : "f"(lf));
    hi = h; lo = l;
}

#define MMA_TF32(c, a, b)                                                         \
    asm volatile("mma.sync.aligned.m16n8k8.row.col.f32.tf32.tf32.f32 "            \
                 "{%0,%1,%2,%3},{%4,%5,%6,%7},{%8,%9},{%0,%1,%2,%3};"             \
                 : "+f"(c[0]), "+f"(c[1]), "+f"(c[2]), "+f"(c[3])                 \
                 : "r"(a[0]), "r"(a[1]), "r"(a[2]), "r"(a[3]),                    \
                   "r"(b[0]), "r"(b[1]))

// ---------------- tensor-core tf32 GEMM, 128x128x16 tile, 3x split -----------
// C[M,N] = A[M,K] @ B (+bias). NT: B row-major [N,K] (C = A·B^T).
// CONCAT: A cols 0..255 from A, 256..511 from A2 (both lda=256).
// smem k-major [16][136] for A and B: conflict-free STS and fragment LDS.
template<bool NT, bool BIAS, bool CONCAT>
__global__ void __launch_bounds__(256, 1) gemm_tc(
    const float* __restrict__ A, const float* __restrict__ A2,
    const float* __restrict__ B, float* __restrict__ C,
    const float* __restrict__ bias,
    int M, int N, int K, int lda, int ldb, int ldc,
    long sA, long sB, long sC)
{
    A += (long)blockIdx.z * sA;
    B += (long)blockIdx.z * sB;
    C += (long)blockIdx.z * sC;

    __shared__ unsigned As_hi[16][136], As_lo[16][136];
    __shared__ unsigned Bs_hi[16][136], Bs_lo[16][136];

    const int tid  = threadIdx.x;
    const int lane = tid & 31;
    const int warp = tid >> 5;
    const int m0 = blockIdx.y * 128;
    const int n0 = blockIdx.x * 128;
    const int wm = (warp >> 2) * 64;
    const int wn = (warp & 3) * 32;
    const int gq = lane >> 2;     // 0..7
    const int tg = lane & 3;      // 0..3

    // A load mapping: row ar (lanes span m), k-quads aq and aq+8
    const int ar = tid & 127;
    const int aq = (tid >> 7) * 4;        // 0 or 4
    // B NN: row bk / bk+8 (k), 4 consecutive n
    const int bk = tid >> 5;              // 0..7
    const int bn = (tid & 31) * 4;
    // B NT: row bn_t (lanes span n), k-quads bq and bq+8
    const int bn_t = tid & 127;
    const int bq   = (tid >> 7) * 4;      // 0 or 4

    float acc[4][4][4];
    #pragma unroll
    for (int i = 0; i < 4; ++i)
        #pragma unroll
        for (int j = 0; j < 4; ++j)
            #pragma unroll
            for (int q = 0; q < 4; ++q) acc[i][j][q] = 0.f;

    float4 va0, va1, vb0, vb1;
    auto load_tile = [&](int k0) {
        const float* Ab = A;
        int kc = k0;
        if (CONCAT) { if (k0 >= 256) { Ab = A2; kc = k0 - 256; } }
        va0 = *(const float4*)(Ab + (long)(m0 + ar) * lda + kc + aq);
        va1 = *(const float4*)(Ab + (long)(m0 + ar) * lda + kc + aq + 8);
        if (NT) {
            vb0 = *(const float4*)(B + (long)(n0 + bn_t) * ldb + k0 + bq);
            vb1 = *(const float4*)(B + (long)(n0 + bn_t) * ldb + k0 + bq + 8);
        } else {
            vb0 = *(const float4*)(B + (long)(k0 + bk) * ldb + n0 + bn);
            vb1 = *(const float4*)(B + (long)(k0 + bk + 8) * ldb + n0 + bn);
        }
    };

    load_tile(0);

    for (int k0 = 0; k0 < K; k0 += 16) {
        __syncthreads();
        {
            // A: store transposed [k][m], STS.32 with lanes spanning m
            float av[4] = {va0.x, va0.y, va0.z, va0.w};
            float aw[4] = {va1.x, va1.y, va1.z, va1.w};
            #pragma unroll
            for (int q = 0; q < 4; ++q) {
                split_tf32(av[q], As_hi[aq + q][ar],     As_lo[aq + q][ar]);
                split_tf32(aw[q], As_hi[aq + 8 + q][ar], As_lo[aq + 8 + q][ar]);
            }
            if (NT) {
                float bv[4] = {vb0.x, vb0.y, vb0.z, vb0.w};
                float bw[4] = {vb1.x, vb1.y, vb1.z, vb1.w};
                #pragma unroll
                for (int q = 0; q < 4; ++q) {
                    split_tf32(bv[q], Bs_hi[bq + q][bn_t],     Bs_lo[bq + q][bn_t]);
                    split_tf32(bw[q], Bs_hi[bq + 8 + q][bn_t], Bs_lo[bq + 8 + q][bn_t]);
                }
            } else {
                // contiguous n quads -> STS.128
                uint4 h0, l0, h1, l1;
                split_tf32(vb0.x, h0.x, l0.x); split_tf32(vb0.y, h0.y, l0.y);
                split_tf32(vb0.z, h0.z, l0.z); split_tf32(vb0.w, h0.w, l0.w);
                split_tf32(vb1.x, h1.x, l1.x); split_tf32(vb1.y, h1.y, l1.y);
                split_tf32(vb1.z, h1.z, l1.z); split_tf32(vb1.w, h1.w, l1.w);
                *(uint4*)&Bs_hi[bk][bn]     = h0;
                *(uint4*)&Bs_lo[bk][bn]     = l0;
                *(uint4*)&Bs_hi[bk + 8][bn] = h1;
                *(uint4*)&Bs_lo[bk + 8][bn] = l1;
            }
        }
        __syncthreads();

        // prefetch next tile during MMA section
        int kn = (k0 + 16 < K) ? k0 + 16 : k0;
        load_tile(kn);

        #pragma unroll
        for (int kk = 0; kk < 16; kk += 8) {
            unsigned ah[4][4], al[4][4], bh[4][2], bl[4][2];
            #pragma unroll
            for (int i = 0; i < 4; ++i) {
                int r = wm + i * 16 + gq;
                ah[i][0] = As_hi[kk + tg    ][r];
                ah[i][1] = As_hi[kk + tg    ][r + 8];
                ah[i][2] = As_hi[kk + tg + 4][r];
                ah[i][3] = As_hi[kk + tg + 4][r + 8];
                al[i][0] = As_lo[kk + tg    ][r];
                al[i][1] = As_lo[kk + tg    ][r + 8];
                al[i][2] = As_lo[kk + tg + 4][r];
                al[i][3] = As_lo[kk + tg + 4][r + 8];
            }
            #pragma unroll
            for (int j = 0; j < 4; ++j) {
                int n = wn + j * 8 + gq;
                bh[j][0] = Bs_hi[kk + tg    ][n];
                bh[j][1] = Bs_hi[kk + tg + 4][n];
                bl[j][0] = Bs_lo[kk + tg    ][n];
                bl[j][1] = Bs_lo[kk + tg + 4][n];
            }
            #pragma unroll
            for (int i = 0; i < 4; ++i)
                #pragma unroll
                for (int j = 0; j < 4; ++j) {
                    MMA_TF32(acc[i][j], ah[i], bh[j]);
                    MMA_TF32(acc[i][j], al[i], bh[j]);
                    MMA_TF32(acc[i][j], ah[i], bl[j]);
                }
        }
    }

    #pragma unroll
    for (int i = 0; i < 4; ++i)
        #pragma unroll
        for (int j = 0; j < 4; ++j) {
            int m = m0 + wm + i * 16 + gq;
            int n = n0 + wn + j * 8 + 2 * tg;
            float2 v0 = make_float2(acc[i][j][0], acc[i][j][1]);
            float2 v1 = make_float2(acc[i][j][2], acc[i][j][3]);
            if (BIAS) {
                float b0 = bias[n], b1 = bias[n + 1];
                v0.x += b0; v0.y += b1;
                v1.x += b0; v1.y += b1;
            }
            *(float2*)(C + (long)m * ldc + n)       = v0;
            *(float2*)(C + (long)(m + 8) * ldc + n) = v1;
        }
}

// ---------------- softmax over rows of length 512 ----------
__global__ void __launch_bounds__(128) softmax_k(float* __restrict__ S)
{
    float* p = S + (long)blockIdx.x * 512;
    int tid = threadIdx.x;
    float v[4];
    float m = -1e30f;
    #pragma unroll
    for (int i = 0; i < 4; ++i) { v[i] = p[tid + 128 * i] * 0.0625f; m = fmaxf(m, v[i]); }
    __shared__ float red[128];
    red[tid] = m; __syncthreads();
    for (int s = 64; s > 0; s >>= 1) { if (tid < s) red[tid] = fmaxf(red[tid], red[tid + s]); __syncthreads(); }
    m = red[0]; __syncthreads();
    float sum = 0.f;
    #pragma unroll
    for (int i = 0; i < 4; ++i) { v[i] = expf(v[i] - m); sum += v[i]; }
    red[tid] = sum; __syncthreads();
    for (int s = 64; s > 0; s >>= 1) { if (tid < s) red[tid] += red[tid + s]; __syncthreads(); }
    float inv = 1.f / red[0];
    #pragma unroll
    for (int i = 0; i < 4; ++i) p[tid + 128 * i] = v[i] * inv;
}

// ---------------- pack weights ----------------
__global__ void pack_init_k(const float* __restrict__ Wf, const float* __restrict__ Wi,
                            const float* __restrict__ Wu, const float* __restrict__ Wo,
                            const float* __restrict__ bf, const float* __restrict__ bi,
                            const float* __restrict__ bu, const float* __restrict__ bo)
{
    int idx = blockIdx.x * blockDim.x + threadIdx.x;
    int nt = gridDim.x * blockDim.x;
    // recurrent weights: [rank][k][jl][g]
    for (int i = idx; i < CLU * 256 * 32 * 4; i += nt) {
        int r  = i >> 15;
        int k  = (i >> 7) & 255;
        int jl = (i >> 2) & 31;
        int g  = i & 3;
        const float* W = (g == 0) ? Wf : (g == 1) ? Wi : (g == 2) ? Wu : Wo;
        g_WhC[i] = W[(E_ + k) * H_ + r * 32 + jl];
    }
    // fused PRE weights: g_Wall[k][g*256+j]
    for (int i = idx; i < 512 * 1024; i += nt) {
        int k = i >> 10;
        int col = i & 1023;
        int g = col >> 8, j = col & 255;
        const float* W = (g == 0) ? Wf : (g == 1) ? Wi : (g == 2) ? Wu : Wo;
        g_Wall[i] = W[k * 256 + j];
    }
    for (int i = idx; i < 1024; i += nt) {
        int g = i >> 8;
        const float* b = (g == 0) ? bf : (g == 1) ? bi : (g == 2) ? bu : bo;
        g_ball[i] = b[i & 255];
    }
}

__device__ __forceinline__ float sigf(float x)  { return 1.f / (1.f + __expf(-x)); }
__device__ __forceinline__ float tanhf_(float x){ return 2.f / (1.f + __expf(-2.f * x)) - 1.f; }

// ---------------- cluster LSTM recurrence (proven R3 version) ----------------
__global__ void __launch_bounds__(256, 1) __cluster_dims__(CLU, 1, 1)
recur2_k(const float* __restrict__ PRE, float* __restrict__ out)
{
    extern __shared__ float4 sm4[];
    float4* ws4   = sm4;            // [256 k][32 jl] (gate4)   8192 fl4
    float4* hs4   = sm4 + 8192;     // [2 buf][256 k] (b4)       512 fl4
    float4* part4 = sm4 + 8704;     // [4 b][8 ks][32 jl]       1024 fl4

    const int tid = threadIdx.x;
    unsigned rank;
    asm("mov.u32 %0, %%cluster_ctarank;" : "=r"(rank));
    const int bg0 = (blockIdx.x / CLU) * BG;

    const float4* Wsrc = (const float4*)g_WhC + (long)rank * 8192;
    for (int m = tid; m < 8192; m += 256) ws4[m] = Wsrc[m];
    for (int m = tid; m < 512; m += 256) hs4[m] = make_float4(0.f, 0.f, 0.f, 0.f);

    const int jl = tid & 31;
    const int ks = tid >> 5;

    const bool epi = tid < 128;
    const int  eb  = tid & 3;
    const int  ejl = tid >> 2;
    const int  jg  = rank * 32 + ejl;

    float creg = 0.f, hlast = 0.f;
    float pre0 = 0.f, pre1 = 0.f, pre2 = 0.f, pre3 = 0.f;
    if (epi) {
        const float* pp = PRE + ((long)0 * B_ + bg0 + eb) * 1024 + jg;
        pre0 = pp[0]; pre1 = pp[256]; pre2 = pp[512]; pre3 = pp[768];
    }

    const unsigned hs_u32 = (unsigned)__cvta_generic_to_shared(hs4);

    asm volatile("barrier.cluster.arrive.aligned;" ::: "memory");
    asm volatile("barrier.cluster.wait.aligned;"   ::: "memory");

    for (int t = 0; t < T_; ++t) {
        const int buf = t & 1;
        const float4* hp = hs4 + buf * 256 + ks * 32;
        const float4* wp = ws4 + (ks * 32) * 32 + jl;

        float4 a0 = {0,0,0,0}, a1 = {0,0,0,0}, a2 = {0,0,0,0}, a3 = {0,0,0,0};
        #pragma unroll 8
        for (int u = 0; u < 32; ++u) {
            float4 hv = hp[u];
            float4 wv = wp[u * 32];
            a0.x += hv.x*wv.x; a0.y += hv.x*wv.y; a0.z += hv.x*wv.z; a0.w += hv.x*wv.w;
            a1.x += hv.y*wv.x; a1.y += hv.y*wv.y; a1.z += hv.y*wv.z; a1.w += hv.y*wv.w;
            a2.x += hv.z*wv.x; a2.y += hv.z*wv.y; a2.z += hv.z*wv.z; a2.w += hv.z*wv.w;
            a3.x += hv.w*wv.x; a3.y += hv.w*wv.y; a3.z += hv.w*wv.z; a3.w += hv.w*wv.w;
        }
        part4[(0 * 8 + ks) * 32 + jl] = a0;
        part4[(1 * 8 + ks) * 32 + jl] = a1;
        part4[(2 * 8 + ks) * 32 + jl] = a2;
        part4[(3 * 8 + ks) * 32 + jl] = a3;
        __syncthreads();

        if (epi) {
            float4 s = part4[(eb * 8 + 0) * 32 + ejl];
            #pragma unroll
            for (int q = 1; q < 8; ++q) {
                float4 p = part4[(eb * 8 + q) * 32 + ejl];
                s.x += p.x; s.y += p.y; s.z += p.z; s.w += p.w;
            }
            float fg = sigf  (s.x + pre0);
            float ig = sigf  (s.y + pre1);
            float ug = tanhf_(s.z + pre2);
            float og = sigf  (s.w + pre3);
            creg  = fg * creg + ig * ug;
            hlast = og * tanhf_(creg);
            out[((long)t * B_ + bg0 + eb) * H_ + jg] = hlast;

            unsigned laddr = hs_u32 + ((((buf ^ 1) * 256 + jg) * 4 + eb) << 2);
            #pragma unroll
            for (int r2 = 0; r2 < CLU; ++r2) {
                unsigned ra;
                asm volatile("mapa.shared::cluster.u32 %0, %1, %2;"
                             : "=r"(ra) : "r"(laddr), "r"(r2));
                asm volatile("st.shared::cluster.f32 [%0], %1;"
                             :: "r"(ra), "f"(hlast) : "memory");
            }

            int tn = (t < T_ - 1) ? t + 1 : t;
            const float* pp = PRE + ((long)tn * B_ + bg0 + eb) * 1024 + jg;
            pre0 = pp[0]; pre1 = pp[256]; pre2 = pp[512]; pre3 = pp[768];
        }

        asm volatile("barrier.cluster.arrive.aligned;" ::: "memory");
        asm volatile("barrier.cluster.wait.aligned;"   ::: "memory");
    }

    if (epi) {
        out[(long)TB_ * H_ + (bg0 + eb) * H_ + jg] = hlast;                 // hx
        out[(long)TB_ * H_ + (long)B_ * H_ + (bg0 + eb) * H_ + jg] = creg;  // cx
    }
}

// ---------------- launch ----------------
extern "C" void kernel_launch(void* const* d_in, const int* in_sizes, int n_in,
                              void* d_out, int out_size)
{
    const float* inputs = (const float*)d_in[0];
    const float* rot    = (const float*)d_in[1];
    const float* ent    = (const float*)d_in[2];
    const float* Wf = (const float*)d_in[3];  const float* bf = (const float*)d_in[4];
    const float* Wi = (const float*)d_in[5];  const float* bi = (const float*)d_in[6];
    const float* Wu = (const float*)d_in[7];  const float* bu = (const float*)d_in[8];
    const float* Wo = (const float*)d_in[9];  const float* bo = (const float*)d_in[10];
    const float* Wc = (const float*)d_in[11]; const float* bc = (const float*)d_in[12];
    float* out = (float*)d_out;

    float *Q, *K, *S, *CTX, *CP, *PRE, *Wall, *ball;
    cudaGetSymbolAddress((void**)&Q,    g_Q);
    cudaGetSymbolAddress((void**)&K,    g_K);
    cudaGetSymbolAddress((void**)&S,    g_S);
    cudaGetSymbolAddress((void**)&CTX,  g_CTX);
    cudaGetSymbolAddress((void**)&CP,   g_CP);
    cudaGetSymbolAddress((void**)&PRE,  g_PRE);
    cudaGetSymbolAddress((void**)&Wall, g_Wall);
    cudaGetSymbolAddress((void**)&ball, g_ball);

    const int RSMEM = 9728 * 16;  // 152 KB dynamic smem for recur2_k
    cudaFuncSetAttribute(recur2_k, cudaFuncAttributeMaxDynamicSharedMemorySize, RSMEM);

    pack_init_k<<<256, 256>>>(Wf, Wi, Wu, Wo, bf, bi, bu, bo);

    // Q = X @ rot ; K = X @ ent
    gemm_tc<false, false, false><<<dim3(E_ / 128, TB_ / 128, 1), 256>>>(
        inputs, nullptr, rot, Q, nullptr, TB_, E_, E_, E_, E_, E_, 0, 0, 0);
    gemm_tc<false, false, false><<<dim3(E_ / 128, TB_ / 128, 1), 256>>>(
        inputs, nullptr, ent, K, nullptr, TB_, E_, E_, E_, E_, E_, 0, 0, 0);

    // scores_b = Q_b @ K_b^T
    gemm_tc<true, false, false><<<dim3(T_ / 128, T_ / 128, B_), 256>>>(
        Q, nullptr, K, S, nullptr, T_, T_, E_, B_ * E_, B_ * E_, T_,
        (long)E_, (long)E_, (long)T_ * T_);

    softmax_k<<<B_ * T_, 128>>>(S);

    // context_b = S_b @ X_b
    gemm_tc<false, false, false><<<dim3(E_ / 128, T_ / 128, B_), 256>>>(
        S, nullptr, inputs, CTX, nullptr, T_, E_, T_, T_, B_ * E_, B_ * E_,
        (long)T_ * T_, (long)E_, (long)E_);

    // CP = CTX @ Wc + bc
    gemm_tc<false, true, false><<<dim3(H_ / 128, TB_ / 128, 1), 256>>>(
        CTX, nullptr, Wc, CP, bc, TB_, H_, E_, E_, H_, H_, 0, 0, 0);

    // PRE = [X | CP] @ Wall + ball
    gemm_tc<false, true, true><<<dim3(1024 / 128, TB_ / 128, 1), 256>>>(
        inputs, CP, Wall, PRE, ball, TB_, 1024, 512, E_, 1024, 1024, 0, 0, 0);

    recur2_k<<<128, 256, RSMEM>>>(PRE, out);
    (void)in_sizes; (void)n_in; (void)out_size;
}

// round 6
// speedup vs baseline: 1.2665x; 1.1405x over previous
#include <cuda_runtime.h>
#include <math.h>

#define T_  512
#define B_  64
#define E_  256
#define H_  256
#define TB_ (T_ * B_)          // 32768
#define CLU 8                  // CTAs per cluster
#define BGR 8                  // batch elements per cluster (two quads)

// ---------------- static device scratch ----------------
__device__ float g_Q  [TB_ * E_];
__device__ float g_K  [TB_ * E_];
__device__ float g_S  [B_ * T_ * T_];
__device__ float g_CTX[TB_ * E_];
__device__ float g_CP [TB_ * H_];
__device__ float g_PRE[(long)TB_ * 4 * H_];
__device__ float g_Wall[512 * 1024];       // packed [Wf|Wi|Wu|Wo] as (512, 1024)
__device__ float g_ball[1024];
__device__ float g_WhC[CLU * 256 * 32 * 4];// recurrent W: [rank][k][jl][gate4]

// ---------------- bf16 2-split helpers ----------------
// pack (even, odd) -> u32 of two bf16; hi carries leading 8 bits, lo the next 8.
__device__ __forceinline__ void split_bf2(float e, float o, unsigned& hi, unsigned& lo)
{
    unsigned h;
    asm("cvt.rn.bf16x2.f32 %0, %1, %2;" : "=r"(h) : "f"(o), "f"(e));
    float eh = __uint_as_float(h << 16);
    float oh = __uint_as_float(h & 0xffff0000u);
    unsigned l;
    asm("cvt.rn.bf16x2.f32 %0, %1, %2;" : "=r"(l) : "f"(o - oh), "f"(e - eh));
    hi = h; lo = l;
}

#define MMA_BF16(c, a, b)                                                          \
    asm volatile("mma.sync.aligned.m16n8k16.row.col.f32.bf16.bf16.f32 "            \
                 "{%0,%1,%2,%3},{%4,%5,%6,%7},{%8,%9},{%0,%1,%2,%3};"              \
                 : "+f"(c[0]), "+f"(c[1]), "+f"(c[2]), "+f"(c[3])                  \
                 : "r"(a[0]), "r"(a[1]), "r"(a[2]), "r"(a[3]),                     \
                   "r"(b[0]), "r"(b[1]))

// ---------------- tensor-core bf16 GEMM, 128x128x16 tile, 3x split -----------
// C[M,N] = A[M,K] @ B (+bias). NT: B row-major [N,K] (C = A·B^T).
// CONCAT: A cols 0..255 from A, 256..511 from A2 (both lda=256).
// smem: k-pair major [8][136] u32 (each u32 = bf16x2 along k).
template<bool NT, bool BIAS, bool CONCAT>
__global__ void __launch_bounds__(256, 1) gemm_tc(
    const float* __restrict__ A, const float* __restrict__ A2,
    const float* __restrict__ B, float* __restrict__ C,
    const float* __restrict__ bias,
    int M, int N, int K, int lda, int ldb, int ldc,
    long sA, long sB, long sC)
{
    A += (long)blockIdx.z * sA;
    B += (long)blockIdx.z * sB;
    C += (long)blockIdx.z * sC;

    __shared__ unsigned As_hi[8][136], As_lo[8][136];
    __shared__ unsigned Bs_hi[8][136], Bs_lo[8][136];

    const int tid  = threadIdx.x;
    const int lane = tid & 31;
    const int warp = tid >> 5;
    const int m0 = blockIdx.y * 128;
    const int n0 = blockIdx.x * 128;
    const int wm = (warp >> 2) * 64;
    const int wn = (warp & 3) * 32;
    const int gq = lane >> 2;     // 0..7
    const int tg = lane & 3;      // 0..3

    // A load: row ar (lanes span m), k-quads aq and aq+8
    const int ar = tid & 127;
    const int aq = (tid >> 7) * 4;        // 0 or 4
    // B NN: even/odd k rows 2*bkr, 2*bkr+1; 4 consecutive n
    const int bkr = tid >> 5;             // 0..7
    const int bn  = (tid & 31) * 4;
    // B NT: row bn_t (lanes span n), k-quads bq and bq+8
    const int bn_t = tid & 127;
    const int bq   = (tid >> 7) * 4;      // 0 or 4

    float acc[4][4][4];
    #pragma unroll
    for (int i = 0; i < 4; ++i)
        #pragma unroll
        for (int j = 0; j < 4; ++j)
            #pragma unroll
            for (int q = 0; q < 4; ++q) acc[i][j][q] = 0.f;

    float4 va0, va1, vb0, vb1;
    auto load_tile = [&](int k0) {
        const float* Ab = A;
        int kc = k0;
        if (CONCAT) { if (k0 >= 256) { Ab = A2; kc = k0 - 256; } }
        va0 = *(const float4*)(Ab + (long)(m0 + ar) * lda + kc + aq);
        va1 = *(const float4*)(Ab + (long)(m0 + ar) * lda + kc + aq + 8);
        if (NT) {
            vb0 = *(const float4*)(B + (long)(n0 + bn_t) * ldb + k0 + bq);
            vb1 = *(const float4*)(B + (long)(n0 + bn_t) * ldb + k0 + bq + 8);
        } else {
            vb0 = *(const float4*)(B + (long)(k0 + 2 * bkr) * ldb + n0 + bn);     // even k
            vb1 = *(const float4*)(B + (long)(k0 + 2 * bkr + 1) * ldb + n0 + bn); // odd k
        }
    };

    load_tile(0);

    for (int k0 = 0; k0 < K; k0 += 16) {
        __syncthreads();
        {
            // A: pairs along k, lanes span m -> conflict-free STS.32
            int kp = aq >> 1;
            split_bf2(va0.x, va0.y, As_hi[kp    ][ar], As_lo[kp    ][ar]);
            split_bf2(va0.z, va0.w, As_hi[kp + 1][ar], As_lo[kp + 1][ar]);
            split_bf2(va1.x, va1.y, As_hi[kp + 4][ar], As_lo[kp + 4][ar]);
            split_bf2(va1.z, va1.w, As_hi[kp + 5][ar], As_lo[kp + 5][ar]);
            if (NT) {
                int bp = bq >> 1;
                split_bf2(vb0.x, vb0.y, Bs_hi[bp    ][bn_t], Bs_lo[bp    ][bn_t]);
                split_bf2(vb0.z, vb0.w, Bs_hi[bp + 1][bn_t], Bs_lo[bp + 1][bn_t]);
                split_bf2(vb1.x, vb1.y, Bs_hi[bp + 4][bn_t], Bs_lo[bp + 4][bn_t]);
                split_bf2(vb1.z, vb1.w, Bs_hi[bp + 5][bn_t], Bs_lo[bp + 5][bn_t]);
            } else {
                // pair across the two k rows; 4 consecutive n -> STS.128
                uint4 h4, l4;
                split_bf2(vb0.x, vb1.x, h4.x, l4.x);
                split_bf2(vb0.y, vb1.y, h4.y, l4.y);
                split_bf2(vb0.z, vb1.z, h4.z, l4.z);
                split_bf2(vb0.w, vb1.w, h4.w, l4.w);
                *(uint4*)&Bs_hi[bkr][bn] = h4;
                *(uint4*)&Bs_lo[bkr][bn] = l4;
            }
        }
        __syncthreads();

        // prefetch next tile during MMA section
        int kn = (k0 + 16 < K) ? k0 + 16 : k0;
        load_tile(kn);

        unsigned ah[4][4], al[4][4], bh[4][2], bl[4][2];
        #pragma unroll
        for (int i = 0; i < 4; ++i) {
            int r = wm + i * 16 + gq;
            ah[i][0] = As_hi[tg    ][r];
            ah[i][1] = As_hi[tg    ][r + 8];
            ah[i][2] = As_hi[tg + 4][r];
            ah[i][3] = As_hi[tg + 4][r + 8];
            al[i][0] = As_lo[tg    ][r];
            al[i][1] = As_lo[tg    ][r + 8];
            al[i][2] = As_lo[tg + 4][r];
            al[i][3] = As_lo[tg + 4][r + 8];
        }
        #pragma unroll
        for (int j = 0; j < 4; ++j) {
            int n = wn + j * 8 + gq;
            bh[j][0] = Bs_hi[tg    ][n];
            bh[j][1] = Bs_hi[tg + 4][n];
            bl[j][0] = Bs_lo[tg    ][n];
            bl[j][1] = Bs_lo[tg + 4][n];
        }
        #pragma unroll
        for (int i = 0; i < 4; ++i)
            #pragma unroll
            for (int j = 0; j < 4; ++j) {
                MMA_BF16(acc[i][j], ah[i], bh[j]);
                MMA_BF16(acc[i][j], al[i], bh[j]);
                MMA_BF16(acc[i][j], ah[i], bl[j]);
            }
    }

    #pragma unroll
    for (int i = 0; i < 4; ++i)
        #pragma unroll
        for (int j = 0; j < 4; ++j) {
            int m = m0 + wm + i * 16 + gq;
            int n = n0 + wn + j * 8 + 2 * tg;
            float2 v0 = make_float2(acc[i][j][0], acc[i][j][1]);
            float2 v1 = make_float2(acc[i][j][2], acc[i][j][3]);
            if (BIAS) {
                float b0 = bias[n], b1 = bias[n + 1];
                v0.x += b0; v0.y += b1;
                v1.x += b0; v1.y += b1;
            }
            *(float2*)(C + (long)m * ldc + n)       = v0;
            *(float2*)(C + (long)(m + 8) * ldc + n) = v1;
        }
}

// ---------------- softmax over rows of length 512 ----------
__global__ void __launch_bounds__(128) softmax_k(float* __restrict__ S)
{
    float* p = S + (long)blockIdx.x * 512;
    int tid = threadIdx.x;
    float v[4];
    float m = -1e30f;
    #pragma unroll
    for (int i = 0; i < 4; ++i) { v[i] = p[tid + 128 * i] * 0.0625f; m = fmaxf(m, v[i]); }
    __shared__ float red[128];
    red[tid] = m; __syncthreads();
    for (int s = 64; s > 0; s >>= 1) { if (tid < s) red[tid] = fmaxf(red[tid], red[tid + s]); __syncthreads(); }
    m = red[0]; __syncthreads();
    float sum = 0.f;
    #pragma unroll
    for (int i = 0; i < 4; ++i) { v[i] = expf(v[i] - m); sum += v[i]; }
    red[tid] = sum; __syncthreads();
    for (int s = 64; s > 0; s >>= 1) { if (tid < s) red[tid] += red[tid + s]; __syncthreads(); }
    float inv = 1.f / red[0];
    #pragma unroll
    for (int i = 0; i < 4; ++i) p[tid + 128 * i] = v[i] * inv;
}

// ---------------- pack weights ----------------
__global__ void pack_init_k(const float* __restrict__ Wf, const float* __restrict__ Wi,
                            const float* __restrict__ Wu, const float* __restrict__ Wo,
                            const float* __restrict__ bf, const float* __restrict__ bi,
                            const float* __restrict__ bu, const float* __restrict__ bo)
{
    int idx = blockIdx.x * blockDim.x + threadIdx.x;
    int nt = gridDim.x * blockDim.x;
    for (int i = idx; i < CLU * 256 * 32 * 4; i += nt) {
        int r  = i >> 15;
        int k  = (i >> 7) & 255;
        int jl = (i >> 2) & 31;
        int g  = i & 3;
        const float* W = (g == 0) ? Wf : (g == 1) ? Wi : (g == 2) ? Wu : Wo;
        g_WhC[i] = W[(E_ + k) * H_ + r * 32 + jl];
    }
    for (int i = idx; i < 512 * 1024; i += nt) {
        int k = i >> 10;
        int col = i & 1023;
        int g = col >> 8, j = col & 255;
        const float* W = (g == 0) ? Wf : (g == 1) ? Wi : (g == 2) ? Wu : Wo;
        g_Wall[i] = W[k * 256 + j];
    }
    for (int i = idx; i < 1024; i += nt) {
        int g = i >> 8;
        const float* b = (g == 0) ? bf : (g == 1) ? bi : (g == 2) ? bu : bo;
        g_ball[i] = b[i & 255];
    }
}

__device__ __forceinline__ float sigf(float x)  { return 1.f / (1.f + __expf(-x)); }
__device__ __forceinline__ float tanhf_(float x){ return 2.f / (1.f + __expf(-2.f * x)) - 1.f; }

#define CARRIVE() asm volatile("barrier.cluster.arrive.aligned;" ::: "memory")
#define CWAIT()   asm volatile("barrier.cluster.wait.aligned;"   ::: "memory")

// ---------------- cluster LSTM recurrence, 2 interleaved batch quads ----------
// 8 clusters x 8 CTAs. Cluster owns 8 batches: quad A (bg0..+3), quad B (+4..+7).
// Split cluster barriers: each wait is covered by the other quad's compute phase.
__global__ void __launch_bounds__(256, 1) __cluster_dims__(CLU, 1, 1)
recur4_k(const float* __restrict__ PRE, float* __restrict__ out)
{
    extern __shared__ float4 sm4[];
    float4* ws4  = sm4;             // [256 k][32 jl] (gate4)   8192 fl4
    float4* hsA  = sm4 + 8192;      // [2 buf][256 j] (b4)       512 fl4
    float4* hsB  = sm4 + 8704;      // [2 buf][256 j] (b4)       512 fl4
    float4* part = sm4 + 9216;      // [4 b][8 ks][32 jl]       1024 fl4

    const int tid = threadIdx.x;
    unsigned rank;
    asm("mov.u32 %0, %%cluster_ctarank;" : "=r"(rank));
    const int bg0 = (blockIdx.x >> 3) * BGR;

    const float4* Wsrc = (const float4*)g_WhC + (long)rank * 8192;
    for (int m = tid; m < 8192; m += 256) ws4[m] = Wsrc[m];
    for (int m = tid; m < 512; m += 256) {
        hsA[m] = make_float4(0.f, 0.f, 0.f, 0.f);
        hsB[m] = make_float4(0.f, 0.f, 0.f, 0.f);
    }

    const int jl = tid & 31;
    const int ks = tid >> 5;

    const bool epi = tid < 128;
    const int  eb  = tid & 3;
    const int  ejl = tid >> 2;
    const int  jg  = rank * 32 + ejl;

    float cA = 0.f, hA = 0.f, cB = 0.f, hB = 0.f;
    float pA0 = 0.f, pA1 = 0.f, pA2 = 0.f, pA3 = 0.f;
    float pB0 = 0.f, pB1 = 0.f, pB2 = 0.f, pB3 = 0.f;
    if (epi) {
        const float* pp = PRE + ((long)0 * B_ + bg0 + eb) * 1024 + jg;
        pA0 = pp[0]; pA1 = pp[256]; pA2 = pp[512]; pA3 = pp[768];
        const float* qq = PRE + ((long)0 * B_ + bg0 + 4 + eb) * 1024 + jg;
        pB0 = qq[0]; pB1 = qq[256]; pB2 = qq[512]; pB3 = qq[768];
    }

    const unsigned hsA_u32 = (unsigned)__cvta_generic_to_shared(hsA);
    const unsigned hsB_u32 = (unsigned)__cvta_generic_to_shared(hsB);

    __syncthreads();
    CARRIVE(); CWAIT();   // init: all CTAs' buffers zeroed before any publish
    CARRIVE();            // open pipeline phase

    for (int t = 0; t < T_; ++t) {
        const int buf = t & 1;

        // ---------- quad A compute ----------
        {
            const float4* hp = hsA + buf * 256 + ks * 32;
            const float4* wp = ws4 + (ks * 32) * 32 + jl;
            float4 a0 = {0,0,0,0}, a1 = {0,0,0,0}, a2 = {0,0,0,0}, a3 = {0,0,0,0};
            #pragma unroll 8
            for (int u = 0; u < 32; ++u) {
                float4 hv = hp[u];
                float4 wv = wp[u * 32];
                a0.x += hv.x*wv.x; a0.y += hv.x*wv.y; a0.z += hv.x*wv.z; a0.w += hv.x*wv.w;
                a1.x += hv.y*wv.x; a1.y += hv.y*wv.y; a1.z += hv.y*wv.z; a1.w += hv.y*wv.w;
                a2.x += hv.z*wv.x; a2.y += hv.z*wv.y; a2.z += hv.z*wv.z; a2.w += hv.z*wv.w;
                a3.x += hv.w*wv.x; a3.y += hv.w*wv.y; a3.z += hv.w*wv.z; a3.w += hv.w*wv.w;
            }
            part[(0 * 8 + ks) * 32 + jl] = a0;
            part[(1 * 8 + ks) * 32 + jl] = a1;
            part[(2 * 8 + ks) * 32 + jl] = a2;
            part[(3 * 8 + ks) * 32 + jl] = a3;
        }
        __syncthreads();
        if (epi) {
            float4 s = part[(eb * 8 + 0) * 32 + ejl];
            #pragma unroll
            for (int q = 1; q < 8; ++q) {
                float4 p = part[(eb * 8 + q) * 32 + ejl];
                s.x += p.x; s.y += p.y; s.z += p.z; s.w += p.w;
            }
            float fg = sigf  (s.x + pA0);
            float ig = sigf  (s.y + pA1);
            float ug = tanhf_(s.z + pA2);
            float og = sigf  (s.w + pA3);
            cA = fg * cA + ig * ug;
            hA = og * tanhf_(cA);
            out[((long)t * B_ + bg0 + eb) * H_ + jg] = hA;
            unsigned laddr = hsA_u32 + ((((buf ^ 1) * 256 + jg) * 4 + eb) << 2);
            #pragma unroll
            for (int r2 = 0; r2 < CLU; ++r2) {
                unsigned ra;
                asm volatile("mapa.shared::cluster.u32 %0, %1, %2;"
                             : "=r"(ra) : "r"(laddr), "r"(r2));
                asm volatile("st.shared::cluster.f32 [%0], %1;"
                             :: "r"(ra), "f"(hA) : "memory");
            }
            int tn = (t < T_ - 1) ? t + 1 : t;
            const float* pp = PRE + ((long)tn * B_ + bg0 + eb) * 1024 + jg;
            pA0 = pp[0]; pA1 = pp[256]; pA2 = pp[512]; pA3 = pp[768];
        }
        CWAIT();       // completes prior phase: hB(t) publishes visible
        CARRIVE();     // opens phase covering hA(t+1) publishes
        __syncthreads();

        // ---------- quad B compute ----------
        {
            const float4* hp = hsB + buf * 256 + ks * 32;
            const float4* wp = ws4 + (ks * 32) * 32 + jl;
            float4 a0 = {0,0,0,0}, a1 = {0,0,0,0}, a2 = {0,0,0,0}, a3 = {0,0,0,0};
            #pragma unroll 8
            for (int u = 0; u < 32; ++u) {
                float4 hv = hp[u];
                float4 wv = wp[u * 32];
                a0.x += hv.x*wv.x; a0.y += hv.x*wv.y; a0.z += hv.x*wv.z; a0.w += hv.x*wv.w;
                a1.x += hv.y*wv.x; a1.y += hv.y*wv.y; a1.z += hv.y*wv.z; a1.w += hv.y*wv.w;
                a2.x += hv.z*wv.x; a2.y += hv.z*wv.y; a2.z += hv.z*wv.z; a2.w += hv.z*wv.w;
                a3.x += hv.w*wv.x; a3.y += hv.w*wv.y; a3.z += hv.w*wv.z; a3.w += hv.w*wv.w;
            }
            part[(0 * 8 + ks) * 32 + jl] = a0;
            part[(1 * 8 + ks) * 32 + jl] = a1;
            part[(2 * 8 + ks) * 32 + jl] = a2;
            part[(3 * 8 + ks) * 32 + jl] = a3;
        }
        __syncthreads();
        if (epi) {
            float4 s = part[(eb * 8 + 0) * 32 + ejl];
            #pragma unroll
            for (int q = 1; q < 8; ++q) {
                float4 p = part[(eb * 8 + q) * 32 + ejl];
                s.x += p.x; s.y += p.y; s.z += p.z; s.w += p.w;
            }
            float fg = sigf  (s.x + pB0);
            float ig = sigf  (s.y + pB1);
            float ug = tanhf_(s.z + pB2);
            float og = sigf  (s.w + pB3);
            cB = fg * cB + ig * ug;
            hB = og * tanhf_(cB);
            out[((long)t * B_ + bg0 + 4 + eb) * H_ + jg] = hB;
            unsigned laddr = hsB_u32 + ((((buf ^ 1) * 256 + jg) * 4 + eb) << 2);
            #pragma unroll
            for (int r2 = 0; r2 < CLU; ++r2) {
                unsigned ra;
                asm volatile("mapa.shared::cluster.u32 %0, %1, %2;"
                             : "=r"(ra) : "r"(laddr), "r"(r2));
                asm volatile("st.shared::cluster.f32 [%0], %1;"
                             :: "r"(ra), "f"(hB) : "memory");
            }
            int tn = (t < T_ - 1) ? t + 1 : t;
            const float* qq = PRE + ((long)tn * B_ + bg0 + 4 + eb) * 1024 + jg;
            pB0 = qq[0]; pB1 = qq[256]; pB2 = qq[512]; pB3 = qq[768];
        }
        CWAIT();       // completes phase of hA(t+1) -> visible next iteration
        CARRIVE();     // opens phase covering hB(t+1)
        __syncthreads();
    }
    CWAIT();           // match final arrive

    if (epi) {
        out[(long)TB_ * H_ + (bg0 + eb) * H_ + jg] = hA;
        out[(long)TB_ * H_ + (bg0 + 4 + eb) * H_ + jg] = hB;
        out[(long)TB_ * H_ + (long)B_ * H_ + (bg0 + eb) * H_ + jg] = cA;
        out[(long)TB_ * H_ + (long)B_ * H_ + (bg0 + 4 + eb) * H_ + jg] = cB;
    }
}

// ---------------- launch ----------------
extern "C" void kernel_launch(void* const* d_in, const int* in_sizes, int n_in,
                              void* d_out, int out_size)
{
    const float* inputs = (const float*)d_in[0];
    const float* rot    = (const float*)d_in[1];
    const float* ent    = (const float*)d_in[2];
    const float* Wf = (const float*)d_in[3];  const float* bf = (const float*)d_in[4];
    const float* Wi = (const float*)d_in[5];  const float* bi = (const float*)d_in[6];
    const float* Wu = (const float*)d_in[7];  const float* bu = (const float*)d_in[8];
    const float* Wo = (const float*)d_in[9];  const float* bo = (const float*)d_in[10];
    const float* Wc = (const float*)d_in[11]; const float* bc = (const float*)d_in[12];
    float* out = (float*)d_out;

    float *Q, *K, *S, *CTX, *CP, *PRE, *Wall, *ball;
    cudaGetSymbolAddress((void**)&Q,    g_Q);
    cudaGetSymbolAddress((void**)&K,    g_K);
    cudaGetSymbolAddress((void**)&S,    g_S);
    cudaGetSymbolAddress((void**)&CTX,  g_CTX);
    cudaGetSymbolAddress((void**)&CP,   g_CP);
    cudaGetSymbolAddress((void**)&PRE,  g_PRE);
    cudaGetSymbolAddress((void**)&Wall, g_Wall);
    cudaGetSymbolAddress((void**)&ball, g_ball);

    const int RSMEM = (8192 + 512 + 512 + 1024) * 16;   // 163840 B
    cudaFuncSetAttribute(recur4_k, cudaFuncAttributeMaxDynamicSharedMemorySize, RSMEM);

    pack_init_k<<<256, 256>>>(Wf, Wi, Wu, Wo, bf, bi, bu, bo);

    // Q = X @ rot ; K = X @ ent
    gemm_tc<false, false, false><<<dim3(E_ / 128, TB_ / 128, 1), 256>>>(
        inputs, nullptr, rot, Q, nullptr, TB_, E_, E_, E_, E_, E_, 0, 0, 0);
    gemm_tc<false, false, false><<<dim3(E_ / 128, TB_ / 128, 1), 256>>>(
        inputs, nullptr, ent, K, nullptr, TB_, E_, E_, E_, E_, E_, 0, 0, 0);

    // scores_b = Q_b @ K_b^T
    gemm_tc<true, false, false><<<dim3(T_ / 128, T_ / 128, B_), 256>>>(
        Q, nullptr, K, S, nullptr, T_, T_, E_, B_ * E_, B_ * E_, T_,
        (long)E_, (long)E_, (long)T_ * T_);

    softmax_k<<<B_ * T_, 128>>>(S);

    // context_b = S_b @ X_b
    gemm_tc<false, false, false><<<dim3(E_ / 128, T_ / 128, B_), 256>>>(
        S, nullptr, inputs, CTX, nullptr, T_, E_, T_, T_, B_ * E_, B_ * E_,
        (long)T_ * T_, (long)E_, (long)E_);

    // CP = CTX @ Wc + bc
    gemm_tc<false, true, false><<<dim3(H_ / 128, TB_ / 128, 1), 256>>>(
        CTX, nullptr, Wc, CP, bc, TB_, H_, E_, E_, H_, H_, 0, 0, 0);

    // PRE = [X | CP] @ Wall + ball
    gemm_tc<false, true, true><<<dim3(1024 / 128, TB_ / 128, 1), 256>>>(
        inputs, CP, Wall, PRE, ball, TB_, 1024, 512, E_, 1024, 1024, 0, 0, 0);

    recur4_k<<<64, 256, RSMEM>>>(PRE, out);
    (void)in_sizes; (void)n_in; (void)out_size;
}